// round 8
// baseline (speedup 1.0000x reference)
#include <cuda_runtime.h>
#include <math.h>

#define L    128
#define NB   64
#define DD   768
#define IN   64
#define OUTD 64
#define NO   32
#define EPSV 1e-8f
#define NCH  16         // l-chunks
#define LCH  8          // l per chunk

// ---------------- scratch (device globals) -----------------------------------
__device__ float g_mu_in[L * NB * IN];                 // (l, n, i)
__device__ float g_fa[L * NB];                         // (l, n)
__device__ float g_Vt[(size_t)NB * L * NO * OUTD];     // (n, l, o, j)  64 MB
__device__ float g_mut[NB * OUTD * NO];                // (n, j, o)
__device__ float g_ivt[NB * OUTD * NO];                // (n, j, o) : 1/(2var+eps)
__device__ float g_a[NB * NO];                         // (n, o) activation logit
__device__ float g_lvp[NB * 8 * NO];                   // (n, jg, o) partial sum log var
__device__ float g_q1[NB * NCH * OUTD * NO];           // chunk partials 8 MB
__device__ float g_q2[NB * NCH * OUTD * NO];           // 8 MB
__device__ float g_q0[NB * NCH * NO];
__device__ float g_qbu[NB * NCH * NO];
__device__ float g_qfa[NB * NCH];

// ---------------- packed f32x2 helpers ---------------------------------------
__device__ __forceinline__ unsigned long long pk(float x, float y) {
    unsigned long long r; asm("mov.b64 %0, {%1, %2};" : "=l"(r) : "f"(x), "f"(y)); return r;
}
__device__ __forceinline__ void fma2(unsigned long long& d, unsigned long long a, unsigned long long b) {
    asm("fma.rn.f32x2 %0, %1, %2, %0;" : "+l"(d) : "l"(a), "l"(b));
}
__device__ __forceinline__ float2 upk(unsigned long long v) {
    float2 r; asm("mov.b64 {%0, %1}, %2;" : "=f"(r.x), "=f"(r.y) : "l"(v)); return r;
}

// ---------------- kernel 1: a_in + mu_in (packed FMA) -------------------------
__global__ __launch_bounds__(256) void front_kernel(
    const float* __restrict__ x,      // (N, L, D)
    const float* __restrict__ Wsc,    // (L, D)
    const float* __restrict__ Bsc,    // (L)
    const float* __restrict__ Wc,     // (L, D, IN)
    const float* __restrict__ Bc)     // (L, IN)
{
    __shared__ __align__(8) float As[32][66];      // [k][n]
    __shared__ __align__(16) float Bs[32][64];     // [k][i]

    const int l   = blockIdx.x;
    const int tid = threadIdx.x;
    const int tn  = tid >> 4;
    const int tj  = tid & 15;

    unsigned long long acc[2][4];
    #pragma unroll
    for (int p = 0; p < 2; p++)
        #pragma unroll
        for (int c = 0; c < 4; c++) acc[p][c] = 0ULL;

    for (int kk = 0; kk < DD; kk += 32) {
        #pragma unroll
        for (int p = 0; p < 8; p++) {
            int e = tid + p * 256;
            int n = e >> 5, k = e & 31;
            As[k][n] = __ldcs(&x[((size_t)n * L + l) * DD + kk + k]);
        }
        #pragma unroll
        for (int p = 0; p < 8; p++) {
            int e = tid + p * 256;
            int k = e >> 6, i = e & 63;
            Bs[k][i] = __ldcs(&Wc[(size_t)l * DD * IN + (size_t)(kk + k) * IN + i]);
        }
        __syncthreads();
        #pragma unroll
        for (int k = 0; k < 32; k++) {
            const float2* ar = reinterpret_cast<const float2*>(&As[k][0]);
            float2 a0 = ar[tn * 2];
            float2 a1 = ar[tn * 2 + 1];
            unsigned long long A0, A1;
            asm("mov.b64 %0, {%1, %2};" : "=l"(A0) : "f"(a0.x), "f"(a0.y));
            asm("mov.b64 %0, {%1, %2};" : "=l"(A1) : "f"(a1.x), "f"(a1.y));
            float4 b = reinterpret_cast<const float4*>(&Bs[k][0])[tj];
            unsigned long long B0 = pk(b.x, b.x), B1 = pk(b.y, b.y),
                               B2 = pk(b.z, b.z), B3 = pk(b.w, b.w);
            fma2(acc[0][0], A0, B0); fma2(acc[0][1], A0, B1);
            fma2(acc[0][2], A0, B2); fma2(acc[0][3], A0, B3);
            fma2(acc[1][0], A1, B0); fma2(acc[1][1], A1, B1);
            fma2(acc[1][2], A1, B2); fma2(acc[1][3], A1, B3);
        }
        __syncthreads();
    }

    #pragma unroll
    for (int p = 0; p < 2; p++) {
        #pragma unroll
        for (int c = 0; c < 4; c++) {
            int i = tj * 4 + c;
            float2 v2 = upk(acc[p][c]);
            float bb = Bc[l * IN + i];
            int n0 = tn * 4 + 2 * p;
            float v0 = v2.x + bb, v1 = v2.y + bb;
            g_mu_in[(size_t)l * NB * IN + (size_t)n0 * IN + i]       = v0 * normcdff(v0);
            g_mu_in[(size_t)l * NB * IN + (size_t)(n0 + 1) * IN + i] = v1 * normcdff(v1);
        }
    }

    const int w = tid >> 5, lane = tid & 31;
    for (int n = w; n < NB; n += 8) {
        float s = 0.f;
        const float* xr = x + ((size_t)n * L + l) * DD;
        const float* wr = Wsc + (size_t)l * DD;
        for (int d = lane; d < DD; d += 32) s += xr[d] * wr[d];
        #pragma unroll
        for (int off = 16; off; off >>= 1) s += __shfl_down_sync(0xffffffffu, s, off);
        if (lane == 0) {
            float a = s + Bsc[l];
            g_fa[l * NB + n] = 1.f / (1.f + expf(-a));
        }
    }
}

// ---------------- kernel 2: votes -> Vt (n,l,o,j) directly ---------------------
__global__ __launch_bounds__(256) void vote_kernel(
    const float* __restrict__ Wv,    // (L, NO, IN, OUT)
    const float* __restrict__ Bv)    // (L, NO, OUT)
{
    __shared__ __align__(8) float As[64][66];      // [i][n]
    __shared__ __align__(16) float Bs[64][64];     // [i][j]

    const int lo  = blockIdx.x;   // l*32 + o
    const int l   = lo >> 5;
    const int o   = lo & 31;
    const int tid = threadIdx.x;

    const float* A = g_mu_in + (size_t)l * NB * IN;
    const float* B = Wv + (size_t)lo * IN * OUTD;

    #pragma unroll
    for (int p = 0; p < 16; p++) {
        int e = tid + p * 256;
        int n = e >> 6, i = e & 63;
        As[i][n] = A[e];
        Bs[e >> 6][e & 63] = __ldcs(&B[e]);
    }
    __syncthreads();

    const int tn = tid >> 4, tj = tid & 15;
    unsigned long long acc[2][4];
    #pragma unroll
    for (int p = 0; p < 2; p++)
        #pragma unroll
        for (int c = 0; c < 4; c++) acc[p][c] = 0ULL;

    #pragma unroll
    for (int i = 0; i < 64; i++) {
        const float2* ar = reinterpret_cast<const float2*>(&As[i][0]);
        float2 a0 = ar[tn * 2];
        float2 a1 = ar[tn * 2 + 1];
        unsigned long long A0, A1;
        asm("mov.b64 %0, {%1, %2};" : "=l"(A0) : "f"(a0.x), "f"(a0.y));
        asm("mov.b64 %0, {%1, %2};" : "=l"(A1) : "f"(a1.x), "f"(a1.y));
        float4 b = reinterpret_cast<const float4*>(&Bs[i][0])[tj];
        unsigned long long B0 = pk(b.x, b.x), B1 = pk(b.y, b.y),
                           B2 = pk(b.z, b.z), B3 = pk(b.w, b.w);
        fma2(acc[0][0], A0, B0); fma2(acc[0][1], A0, B1);
        fma2(acc[0][2], A0, B2); fma2(acc[0][3], A0, B3);
        fma2(acc[1][0], A1, B0); fma2(acc[1][1], A1, B1);
        fma2(acc[1][2], A1, B2); fma2(acc[1][3], A1, B3);
    }

    float4 bias;
    bias.x = __ldcs(&Bv[(size_t)lo * OUTD + tj * 4 + 0]);
    bias.y = __ldcs(&Bv[(size_t)lo * OUTD + tj * 4 + 1]);
    bias.z = __ldcs(&Bv[(size_t)lo * OUTD + tj * 4 + 2]);
    bias.w = __ldcs(&Bv[(size_t)lo * OUTD + tj * 4 + 3]);
    #pragma unroll
    for (int p = 0; p < 2; p++) {
        float2 vx = upk(acc[p][0]), vy = upk(acc[p][1]),
               vz = upk(acc[p][2]), vw = upk(acc[p][3]);
        int n0 = tn * 4 + 2 * p;
        float4 o0 = make_float4(vx.x + bias.x, vy.x + bias.y, vz.x + bias.z, vw.x + bias.w);
        float4 o1 = make_float4(vx.y + bias.x, vy.y + bias.y, vz.y + bias.z, vw.y + bias.w);
        float* r0 = g_Vt + (((size_t)n0 * L + l) * NO + o) * OUTD;
        float* r1 = g_Vt + (((size_t)(n0 + 1) * L + l) * NO + o) * OUTD;
        reinterpret_cast<float4*>(r0)[tj] = o0;
        reinterpret_cast<float4*>(r1)[tj] = o1;
    }
}

// ---------------- kernel 3: fused route + EM partials (lane = o) --------------
// grid = NB*NCH (bid: n = bid>>4, c = bid&15), block = 256 (8 warps, 1 l each).
// uniform=1: E-step 0 (D = fa/32, no logit pass / no V read in phase 1).
__global__ __launch_bounds__(256) void re_kernel(const float* __restrict__ bu,
                                                 int uniform)
{
    __shared__ float s_mu[OUTD * NO];   // (j, o)
    __shared__ float s_iv[OUTD * NO];
    __shared__ float s_C[NO];
    __shared__ float s_D[LCH][NO];

    const int bid = blockIdx.x;
    const int n = bid >> 4, c = bid & (NCH - 1);
    const int tid = threadIdx.x;
    const int w = tid >> 5, lane = tid & 31;

    if (!uniform) {
        const float4* ms = reinterpret_cast<const float4*>(g_mut + (size_t)n * OUTD * NO);
        const float4* is = reinterpret_cast<const float4*>(g_ivt + (size_t)n * OUTD * NO);
        float4* md = reinterpret_cast<float4*>(s_mu);
        float4* id = reinterpret_cast<float4*>(s_iv);
        md[tid] = ms[tid]; md[tid + 256] = ms[tid + 256];
        id[tid] = is[tid]; id[tid + 256] = is[tid + 256];
        if (tid < NO) {
            float a = g_a[n * NO + tid];
            float slv = 0.f;
            #pragma unroll
            for (int k = 0; k < 8; k++) slv += g_lvp[(n * 8 + k) * NO + tid];
            float lsig = (a > 0.f) ? -log1pf(expf(-a)) : a - log1pf(expf(a));
            s_C[tid] = lsig - 1.f - 0.5f * 3.14159265358979323846f - 0.5f * slv;
        }
        __syncthreads();
    }

    // phase 1: warp w -> l = c*8 + w; lane = o; zero barriers
    const int l = c * LCH + w;
    const float fa = g_fa[l * NB + n];
    float D;
    if (uniform) {
        D = fa * (1.f / 32.f);
    } else {
        const float4* vb = reinterpret_cast<const float4*>(
            g_Vt + (((size_t)n * L + l) * NO + lane) * OUTD);
        float t = 0.f;
        #pragma unroll
        for (int jq = 0; jq < 16; jq++) {
            float4 v = vb[jq];
            int j = jq * 4;
            float d0 = v.x - s_mu[(j + 0) * NO + lane];
            float d1 = v.y - s_mu[(j + 1) * NO + lane];
            float d2 = v.z - s_mu[(j + 2) * NO + lane];
            float d3 = v.w - s_mu[(j + 3) * NO + lane];
            t = fmaf(d0 * d0, s_iv[(j + 0) * NO + lane], t);
            t = fmaf(d1 * d1, s_iv[(j + 1) * NO + lane], t);
            t = fmaf(d2 * d2, s_iv[(j + 2) * NO + lane], t);
            t = fmaf(d3 * d3, s_iv[(j + 3) * NO + lane], t);
        }
        float lg = s_C[lane] - t;
        float mx = lg;
        #pragma unroll
        for (int off = 16; off; off >>= 1) mx = fmaxf(mx, __shfl_xor_sync(0xffffffffu, mx, off));
        float e = expf(lg - mx);
        float ss = e;
        #pragma unroll
        for (int off = 16; off; off >>= 1) ss += __shfl_xor_sync(0xffffffffu, ss, off);
        D = fa * (e / ss);
    }
    s_D[w][lane] = D;
    __syncthreads();

    // phase 2: warp w owns j-slice [w*8, w*8+8); lane = o; accumulate over 8 l
    float s1[8] = {}, s2[8] = {};
    const int j0 = w * 8;
    #pragma unroll
    for (int li = 0; li < LCH; li++) {
        float Dl = s_D[li][lane];
        const float4* vb = reinterpret_cast<const float4*>(
            g_Vt + (((size_t)n * L + c * LCH + li) * NO + lane) * OUTD + j0);
        float4 va = vb[0], vc = vb[1];
        float vv[8] = {va.x, va.y, va.z, va.w, vc.x, vc.y, vc.z, vc.w};
        #pragma unroll
        for (int jj = 0; jj < 8; jj++) {
            float dv = Dl * vv[jj];
            s1[jj] += dv;
            s2[jj] = fmaf(dv, vv[jj], s2[jj]);
        }
    }
    float* q1 = g_q1 + ((size_t)bid * OUTD + j0) * NO + lane;
    float* q2 = g_q2 + ((size_t)bid * OUTD + j0) * NO + lane;
    #pragma unroll
    for (int jj = 0; jj < 8; jj++) { q1[jj * NO] = s1[jj]; q2[jj * NO] = s2[jj]; }

    if (w == 0) {
        float s0 = 0.f, sbu = 0.f, sfa = 0.f;
        #pragma unroll
        for (int li = 0; li < LCH; li++) {
            int ll = c * LCH + li;
            float Dl = s_D[li][lane];
            s0 += Dl;
            sbu = fmaf(bu[ll], Dl, sbu);
            sfa += g_fa[ll * NB + n];
        }
        g_q0[bid * NO + lane]  = s0;
        g_qbu[bid * NO + lane] = sbu;
        if (lane == 0) g_qfa[bid] = sfa;
    }
}

// ---------------- kernel 4: finalize EM (one (j,o) per thread) -----------------
// grid = NB*8 (bid: n = bid>>3, jg = bid&7), block = 256.
// Thread: jj = tid>>5 (0..7), o = tid&31; j = jg*8 + jj.
__global__ __launch_bounds__(256) void fin_kernel(
    const float* __restrict__ bi, int write_out, float* __restrict__ out)
{
    const int bid = blockIdx.x;
    const int n = bid >> 3, jg = bid & 7;
    const int tid = threadIdx.x;
    const int jj = tid >> 5, o = tid & 31;
    const int j = jg * 8 + jj;

    float s0 = 0.f, sbu = 0.f, sfa = 0.f;
    #pragma unroll
    for (int c = 0; c < NCH; c++) {
        s0  += g_q0[(n * NCH + c) * NO + o];
        sbu += g_qbu[(n * NCH + c) * NO + o];
        sfa += g_qfa[n * NCH + c];
    }
    float denom = s0 + EPSV;
    float a = sbu - bi[o] * (sfa - s0);

    float s1 = 0.f, s2 = 0.f;
    #pragma unroll
    for (int c = 0; c < NCH; c++) {
        size_t p = (((size_t)(n * NCH + c)) * OUTD + j) * NO + o;
        s1 += g_q1[p];
        s2 += g_q2[p];
    }
    float m   = s1 / denom;
    float var = fmaxf((s2 - 2.f * m * s1 + m * m * s0) / denom, 0.f);
    g_mut[((size_t)n * OUTD + j) * NO + o] = m;
    g_ivt[((size_t)n * OUTD + j) * NO + o] = 1.f / (2.f * var + EPSV);

    if (write_out) {
        out[NB * NO + ((size_t)n * NO + o) * OUTD + j] = m;    // mu_out (N, NO, OUT)
        if (jj == 0 && jg == 0) out[n * NO + o] = a;           // a_out (N, NO)
    } else {
        float lv = logf(var + EPSV);
        __shared__ float s_lv[8][NO];
        s_lv[jj][o] = lv;
        __syncthreads();
        if (jj == 0) {
            float slv = 0.f;
            #pragma unroll
            for (int k = 0; k < 8; k++) slv += s_lv[k][o];
            g_lvp[(n * 8 + jg) * NO + o] = slv;
            if (jg == 0) g_a[n * NO + o] = a;
        }
    }
}

// ---------------- launch --------------------------------------------------------
extern "C" void kernel_launch(void* const* d_in, const int* in_sizes, int n_in,
                              void* d_out, int out_size)
{
    const float* x      = (const float*)d_in[0];
    const float* Wscore = (const float*)d_in[1];
    const float* Bscore = (const float*)d_in[2];
    const float* Wcap   = (const float*)d_in[3];
    const float* Bcap   = (const float*)d_in[4];
    const float* Wvote  = (const float*)d_in[5];
    const float* Bvote  = (const float*)d_in[6];
    const float* bu     = (const float*)d_in[7];
    const float* bi     = (const float*)d_in[8];
    float* out = (float*)d_out;

    front_kernel<<<L, 256>>>(x, Wscore, Bscore, Wcap, Bcap);
    vote_kernel<<<L * NO, 256>>>(Wvote, Bvote);

    // iters = 3: E0(uniform), route+E ×2
    re_kernel<<<NB * NCH, 256>>>(bu, 1);
    fin_kernel<<<NB * 8, 256>>>(bi, 0, out);
    re_kernel<<<NB * NCH, 256>>>(bu, 0);
    fin_kernel<<<NB * 8, 256>>>(bi, 0, out);
    re_kernel<<<NB * NCH, 256>>>(bu, 0);
    fin_kernel<<<NB * 8, 256>>>(bi, 1, out);
}

// round 9
// speedup vs baseline: 1.3097x; 1.3097x over previous
#include <cuda_runtime.h>
#include <math.h>

#define L    128
#define NB   64
#define DD   768
#define IN   64
#define OUTD 64
#define NO   32
#define EPSV 1e-8f
#define NCH  16         // l-chunks
#define LCH  8          // l per chunk

// ---------------- scratch (device globals) -----------------------------------
__device__ float g_mu_in[L * NB * IN];                 // (l, n, i)
__device__ float g_fa[L * NB];                         // (l, n)
__device__ float g_V [(size_t)L * NO * NB * OUTD];     // (l, o, n, j)  64 MB
__device__ float g_Vt[(size_t)NB * L * OUTD * NO];     // (n, l, j, o)  64 MB
__device__ float g_mut[NB * OUTD * NO];                // (n, j, o)
__device__ float g_ivt[NB * OUTD * NO];                // (n, j, o) : 1/(2var+eps)
__device__ float g_a[NB * NO];                         // (n, o) activation logit
__device__ float g_lvp[NB * 4 * NO];                   // (n, jg, o) partial sum log var
__device__ float g_q1[NB * NCH * OUTD * NO];           // chunk partials 8 MB
__device__ float g_q2[NB * NCH * OUTD * NO];           // 8 MB
__device__ float g_q0[NB * NCH * NO];
__device__ float g_qbu[NB * NCH * NO];
__device__ float g_qfa[NB * NCH];

// ---------------- packed f32x2 helpers ---------------------------------------
__device__ __forceinline__ unsigned long long pk(float x, float y) {
    unsigned long long r; asm("mov.b64 %0, {%1, %2};" : "=l"(r) : "f"(x), "f"(y)); return r;
}
__device__ __forceinline__ void fma2(unsigned long long& d, unsigned long long a, unsigned long long b) {
    asm("fma.rn.f32x2 %0, %1, %2, %0;" : "+l"(d) : "l"(a), "l"(b));
}
__device__ __forceinline__ float2 upk(unsigned long long v) {
    float2 r; asm("mov.b64 {%0, %1}, %2;" : "=f"(r.x), "=f"(r.y) : "l"(v)); return r;
}

// ---------------- kernel 1: a_in + mu_in (n-split 2, fused score) -------------
// grid = L*2 (l = bid>>1, n-half = bid&1), block = 256.
// GEMM: 32(n) x 64(i), K=768. Score dot fused into the k-tile loop via As.
__global__ __launch_bounds__(256) void front_kernel(
    const float* __restrict__ x,      // (N, L, D)
    const float* __restrict__ Wsc,    // (L, D)
    const float* __restrict__ Bsc,    // (L)
    const float* __restrict__ Wc,     // (L, D, IN)
    const float* __restrict__ Bc)     // (L, IN)
{
    __shared__ __align__(8) float As[32][34];      // [k][n-half]  (34: 8B-aligned rows)
    __shared__ __align__(16) float Bs[32][64];     // [k][i]
    __shared__ float s_ws[32];
    __shared__ float s_sc[8][32];

    const int bid = blockIdx.x;
    const int l   = bid >> 1;
    const int n0  = (bid & 1) * 32;
    const int tid = threadIdx.x;
    const int tn  = tid >> 4;   // 0..15 -> n pair (2tn, 2tn+1)
    const int tj  = tid & 15;   // 0..15 -> i quad

    const int sq = tid >> 5, sn = tid & 31;   // score mapping
    float sc = 0.f;

    unsigned long long acc[4] = {};

    for (int kk = 0; kk < DD; kk += 32) {
        #pragma unroll
        for (int p = 0; p < 4; p++) {
            int e = tid + p * 256;
            int n = e >> 5, k = e & 31;
            As[k][n] = __ldcs(&x[((size_t)(n0 + n) * L + l) * DD + kk + k]);
        }
        #pragma unroll
        for (int p = 0; p < 8; p++) {
            int e = tid + p * 256;
            int k = e >> 6, i = e & 63;
            Bs[k][i] = __ldcs(&Wc[(size_t)l * DD * IN + (size_t)(kk + k) * IN + i]);
        }
        if (tid < 32) s_ws[tid] = Wsc[(size_t)l * DD + kk + tid];
        __syncthreads();

        #pragma unroll
        for (int k = 0; k < 32; k++) {
            float2 a0 = reinterpret_cast<const float2*>(&As[k][0])[tn];
            unsigned long long A0;
            asm("mov.b64 %0, {%1, %2};" : "=l"(A0) : "f"(a0.x), "f"(a0.y));
            float4 b = reinterpret_cast<const float4*>(&Bs[k][0])[tj];
            unsigned long long B0 = pk(b.x, b.x), B1 = pk(b.y, b.y),
                               B2 = pk(b.z, b.z), B3 = pk(b.w, b.w);
            fma2(acc[0], A0, B0); fma2(acc[1], A0, B1);
            fma2(acc[2], A0, B2); fma2(acc[3], A0, B3);
        }

        // score partial: thread (sq, sn) handles k-slice [sq*4, sq*4+4) for n0+sn
        #pragma unroll
        for (int k4 = 0; k4 < 4; k4++)
            sc = fmaf(As[sq * 4 + k4][sn], s_ws[sq * 4 + k4], sc);
        __syncthreads();
    }

    // epilogue: bias + exact gelu
    #pragma unroll
    for (int c = 0; c < 4; c++) {
        int i = tj * 4 + c;
        float2 v2 = upk(acc[c]);
        float bb = Bc[l * IN + i];
        int n = n0 + tn * 2;
        float v0 = v2.x + bb, v1 = v2.y + bb;
        g_mu_in[(size_t)l * NB * IN + (size_t)n * IN + i]       = v0 * normcdff(v0);
        g_mu_in[(size_t)l * NB * IN + (size_t)(n + 1) * IN + i] = v1 * normcdff(v1);
    }

    // score reduce: 8 k-slice partials per n
    s_sc[sq][sn] = sc;
    __syncthreads();
    if (tid < 32) {
        float s = Bsc[l];
        #pragma unroll
        for (int q = 0; q < 8; q++) s += s_sc[q][tid];
        g_fa[l * NB + n0 + tid] = 1.f / (1.f + expf(-s));
    }
}

// ---------------- kernel 2: votes V (packed FMA) ------------------------------
__global__ __launch_bounds__(256) void vote_kernel(
    const float* __restrict__ Wv,    // (L, NO, IN, OUT)
    const float* __restrict__ Bv)    // (L, NO, OUT)
{
    __shared__ __align__(8) float As[64][66];      // [i][n]
    __shared__ __align__(16) float Bs[64][64];     // [i][j]

    const int lo  = blockIdx.x;   // l*32 + o
    const int l   = lo >> 5;
    const int tid = threadIdx.x;

    const float* A = g_mu_in + (size_t)l * NB * IN;
    const float* B = Wv + (size_t)lo * IN * OUTD;

    #pragma unroll
    for (int p = 0; p < 16; p++) {
        int e = tid + p * 256;
        int n = e >> 6, i = e & 63;
        As[i][n] = A[e];
        Bs[e >> 6][e & 63] = __ldcs(&B[e]);
    }
    __syncthreads();

    const int tn = tid >> 4, tj = tid & 15;
    unsigned long long acc[2][4];
    #pragma unroll
    for (int p = 0; p < 2; p++)
        #pragma unroll
        for (int c = 0; c < 4; c++) acc[p][c] = 0ULL;

    #pragma unroll
    for (int i = 0; i < 64; i++) {
        const float2* ar = reinterpret_cast<const float2*>(&As[i][0]);
        float2 a0 = ar[tn * 2];
        float2 a1 = ar[tn * 2 + 1];
        unsigned long long A0, A1;
        asm("mov.b64 %0, {%1, %2};" : "=l"(A0) : "f"(a0.x), "f"(a0.y));
        asm("mov.b64 %0, {%1, %2};" : "=l"(A1) : "f"(a1.x), "f"(a1.y));
        float4 b = reinterpret_cast<const float4*>(&Bs[i][0])[tj];
        unsigned long long B0 = pk(b.x, b.x), B1 = pk(b.y, b.y),
                           B2 = pk(b.z, b.z), B3 = pk(b.w, b.w);
        fma2(acc[0][0], A0, B0); fma2(acc[0][1], A0, B1);
        fma2(acc[0][2], A0, B2); fma2(acc[0][3], A0, B3);
        fma2(acc[1][0], A1, B0); fma2(acc[1][1], A1, B1);
        fma2(acc[1][2], A1, B2); fma2(acc[1][3], A1, B3);
    }

    float4 bias;
    bias.x = __ldcs(&Bv[(size_t)lo * OUTD + tj * 4 + 0]);
    bias.y = __ldcs(&Bv[(size_t)lo * OUTD + tj * 4 + 1]);
    bias.z = __ldcs(&Bv[(size_t)lo * OUTD + tj * 4 + 2]);
    bias.w = __ldcs(&Bv[(size_t)lo * OUTD + tj * 4 + 3]);
    float* Vout = g_V + (size_t)lo * NB * OUTD;
    #pragma unroll
    for (int p = 0; p < 2; p++) {
        float2 vx = upk(acc[p][0]), vy = upk(acc[p][1]),
               vz = upk(acc[p][2]), vw = upk(acc[p][3]);
        int n0 = tn * 4 + 2 * p;
        float4 o0 = make_float4(vx.x + bias.x, vy.x + bias.y, vz.x + bias.z, vw.x + bias.w);
        float4 o1 = make_float4(vx.y + bias.x, vy.y + bias.y, vz.y + bias.z, vw.y + bias.w);
        reinterpret_cast<float4*>(Vout + (size_t)n0 * OUTD)[tj]       = o0;
        reinterpret_cast<float4*>(Vout + (size_t)(n0 + 1) * OUTD)[tj] = o1;
    }
}

// ---------------- kernel 2b: fused transpose + uniform E-step -----------------
// grid = NB*NCH (bid: n = bid>>4, c = bid&15), block = 256.
__global__ __launch_bounds__(256) void trE0_kernel(const float* __restrict__ bu)
{
    __shared__ float sm[NO * 65];
    const int bid = blockIdx.x;
    const int n = bid >> 4, c = bid & (NCH - 1);
    const int tid = threadIdx.x;
    const int o = tid & 31, jw = tid >> 5;

    float s1[8] = {}, s2[8] = {};
    float s0 = 0.f, sbu = 0.f, sfa = 0.f;

    for (int li = 0; li < LCH; li++) {
        const int l = c * LCH + li;
        #pragma unroll
        for (int r = 0; r < 2; r++) {
            int idx = tid + r * 256;       // 0..511
            int oo = idx >> 4, f4 = idx & 15;
            float4 v = __ldcs(reinterpret_cast<const float4*>(
                g_V + (((size_t)l * NO + oo) * NB + n) * OUTD) + f4);
            float* d = sm + oo * 65 + f4 * 4;
            d[0] = v.x; d[1] = v.y; d[2] = v.z; d[3] = v.w;
        }
        __syncthreads();

        float fa = g_fa[l * NB + n];
        float D = fa * (1.f / 32.f);
        float* vt = g_Vt + ((size_t)n * L + l) * OUTD * NO;
        #pragma unroll
        for (int k = 0; k < 8; k++) {
            int j = jw * 8 + k;
            float v = sm[o * 65 + j];
            vt[j * NO + o] = v;
            float dv = D * v;
            s1[k] += dv;
            s2[k] = fmaf(dv, v, s2[k]);
        }
        s0 += D; sbu = fmaf(bu[l], D, sbu); sfa += fa;
        __syncthreads();
    }

    const int j0 = jw * 8;
    float* q1 = g_q1 + ((size_t)bid * OUTD + j0) * NO + o;
    float* q2 = g_q2 + ((size_t)bid * OUTD + j0) * NO + o;
    #pragma unroll
    for (int k = 0; k < 8; k++) { q1[k * NO] = s1[k]; q2[k * NO] = s2[k]; }
    if (jw == 0) {
        g_q0[bid * NO + o]  = s0;
        g_qbu[bid * NO + o] = sbu;
        if (o == 0) g_qfa[bid] = sfa;
    }
}

// ---------------- kernel 3: fused route + EM partials (lane = o) --------------
// grid = NB*NCH (bid: n = bid>>4, c = bid&15), block = 256 (8 warps, 1 l each).
__global__ __launch_bounds__(256) void re_kernel(const float* __restrict__ bu)
{
    __shared__ float s_mu[OUTD * NO];   // (j, o)
    __shared__ float s_iv[OUTD * NO];
    __shared__ float s_C[NO];
    __shared__ float s_D[LCH][NO];

    const int bid = blockIdx.x;
    const int n = bid >> 4, c = bid & (NCH - 1);
    const int tid = threadIdx.x;
    const int w = tid >> 5, lane = tid & 31;

    {
        const float4* ms = reinterpret_cast<const float4*>(g_mut + (size_t)n * OUTD * NO);
        const float4* is = reinterpret_cast<const float4*>(g_ivt + (size_t)n * OUTD * NO);
        float4* md = reinterpret_cast<float4*>(s_mu);
        float4* id = reinterpret_cast<float4*>(s_iv);
        md[tid] = ms[tid]; md[tid + 256] = ms[tid + 256];
        id[tid] = is[tid]; id[tid + 256] = is[tid + 256];
        if (tid < NO) {
            float a = g_a[n * NO + tid];
            float slv = g_lvp[(n * 4 + 0) * NO + tid] + g_lvp[(n * 4 + 1) * NO + tid]
                      + g_lvp[(n * 4 + 2) * NO + tid] + g_lvp[(n * 4 + 3) * NO + tid];
            float lsig = (a > 0.f) ? -log1pf(expf(-a)) : a - log1pf(expf(a));
            s_C[tid] = lsig - 1.f - 0.5f * 3.14159265358979323846f - 0.5f * slv;
        }
        __syncthreads();
    }

    // phase 1: warp w -> l = c*8 + w; lane = o; zero barriers
    const int l = c * LCH + w;
    const float fa = g_fa[l * NB + n];
    float D;
    {
        const float* vb = g_Vt + ((size_t)n * L + l) * OUTD * NO + lane;
        float t = 0.f;
        #pragma unroll
        for (int j = 0; j < OUTD; j++) {
            float v = vb[j * NO];
            float d = v - s_mu[j * NO + lane];
            t = fmaf(d * d, s_iv[j * NO + lane], t);
        }
        float lg = s_C[lane] - t;
        float mx = lg;
        #pragma unroll
        for (int off = 16; off; off >>= 1) mx = fmaxf(mx, __shfl_xor_sync(0xffffffffu, mx, off));
        float e = expf(lg - mx);
        float ss = e;
        #pragma unroll
        for (int off = 16; off; off >>= 1) ss += __shfl_xor_sync(0xffffffffu, ss, off);
        D = fa * (e / ss);
    }
    s_D[w][lane] = D;
    __syncthreads();

    // phase 2: warp w owns j-slice [w*8, w*8+8); lane = o; accumulate over 8 l
    float s1[8] = {}, s2[8] = {};
    const int j0 = w * 8;
    #pragma unroll
    for (int li = 0; li < LCH; li++) {
        float Dl = s_D[li][lane];
        const float* vb = g_Vt + (((size_t)n * L + c * LCH + li) * OUTD + j0) * NO + lane;
        #pragma unroll
        for (int jj = 0; jj < 8; jj++) {
            float v = vb[jj * NO];
            float dv = Dl * v;
            s1[jj] += dv;
            s2[jj] = fmaf(dv, v, s2[jj]);
        }
    }
    float* q1 = g_q1 + ((size_t)bid * OUTD + j0) * NO + lane;
    float* q2 = g_q2 + ((size_t)bid * OUTD + j0) * NO + lane;
    #pragma unroll
    for (int jj = 0; jj < 8; jj++) { q1[jj * NO] = s1[jj]; q2[jj * NO] = s2[jj]; }

    if (w == 0) {
        float s0 = 0.f, sbu = 0.f, sfa = 0.f;
        #pragma unroll
        for (int li = 0; li < LCH; li++) {
            int ll = c * LCH + li;
            float Dl = s_D[li][lane];
            s0 += Dl;
            sbu = fmaf(bu[ll], Dl, sbu);
            sfa += g_fa[ll * NB + n];
        }
        g_q0[bid * NO + lane]  = s0;
        g_qbu[bid * NO + lane] = sbu;
        if (lane == 0) g_qfa[bid] = sfa;
    }
}

// ---------------- kernel 4: finalize EM (parallel, one (j,o) per thread) ------
// grid = NB*4 (bid: n = bid>>2, jg = bid&3), block = 512.
__global__ __launch_bounds__(512) void fin_kernel(
    const float* __restrict__ bi, int write_out, float* __restrict__ out)
{
    const int bid = blockIdx.x;
    const int n = bid >> 2, jg = bid & 3;
    const int tid = threadIdx.x;
    const int jj = tid >> 5, o = tid & 31;
    const int j = jg * 16 + jj;

    float s0 = 0.f, sbu = 0.f, sfa = 0.f;
    #pragma unroll
    for (int c = 0; c < NCH; c++) {
        s0  += g_q0[(n * NCH + c) * NO + o];
        sbu += g_qbu[(n * NCH + c) * NO + o];
        sfa += g_qfa[n * NCH + c];
    }
    float denom = s0 + EPSV;
    float a = sbu - bi[o] * (sfa - s0);

    float s1 = 0.f, s2 = 0.f;
    #pragma unroll
    for (int c = 0; c < NCH; c++) {
        size_t p = (((size_t)(n * NCH + c)) * OUTD + j) * NO + o;
        s1 += g_q1[p];
        s2 += g_q2[p];
    }
    float m   = s1 / denom;
    float var = fmaxf((s2 - 2.f * m * s1 + m * m * s0) / denom, 0.f);
    g_mut[((size_t)n * OUTD + j) * NO + o] = m;
    g_ivt[((size_t)n * OUTD + j) * NO + o] = 1.f / (2.f * var + EPSV);

    if (write_out) {
        out[NB * NO + ((size_t)n * NO + o) * OUTD + j] = m;    // mu_out (N, NO, OUT)
        if (jj == 0 && jg == 0) out[n * NO + o] = a;           // a_out (N, NO)
    } else {
        float lv = logf(var + EPSV);
        __shared__ float s_lv[16][NO];
        s_lv[jj][o] = lv;
        __syncthreads();
        if (jj == 0) {
            float slv = 0.f;
            #pragma unroll
            for (int k = 0; k < 16; k++) slv += s_lv[k][o];
            g_lvp[(n * 4 + jg) * NO + o] = slv;
            if (jg == 0) g_a[n * NO + o] = a;
        }
    }
}

// ---------------- launch --------------------------------------------------------
extern "C" void kernel_launch(void* const* d_in, const int* in_sizes, int n_in,
                              void* d_out, int out_size)
{
    const float* x      = (const float*)d_in[0];
    const float* Wscore = (const float*)d_in[1];
    const float* Bscore = (const float*)d_in[2];
    const float* Wcap   = (const float*)d_in[3];
    const float* Bcap   = (const float*)d_in[4];
    const float* Wvote  = (const float*)d_in[5];
    const float* Bvote  = (const float*)d_in[6];
    const float* bu     = (const float*)d_in[7];
    const float* bi     = (const float*)d_in[8];
    float* out = (float*)d_out;

    front_kernel<<<L * 2, 256>>>(x, Wscore, Bscore, Wcap, Bcap);
    vote_kernel<<<L * NO, 256>>>(Wvote, Bvote);

    // iters = 3: E0 fused with transpose, then route+E ×2
    trE0_kernel<<<NB * NCH, 256>>>(bu);
    fin_kernel<<<NB * 4, 512>>>(bi, 0, out);
    re_kernel<<<NB * NCH, 256>>>(bu);
    fin_kernel<<<NB * 4, 512>>>(bi, 0, out);
    re_kernel<<<NB * NCH, 256>>>(bu);
    fin_kernel<<<NB * 4, 512>>>(bi, 1, out);
}